// round 2
// baseline (speedup 1.0000x reference)
#include <cuda_runtime.h>
#include <cstddef>

#define BATCH 32
#define NUU   64
#define NYY   64
#define NXX   512
#define NWW   512
#define TSTEP 1024
#define RCTAS 128
#define RTHR  256

// ---------------- device scratch (__device__ globals: allocation-free) --------
__device__ float d_Cv[NWW * NXX];
__device__ float d_Dv[NWW * NUU];
__device__ float d_X[NXX * NXX];
__device__ float d_X2[NXX * NXX];
__device__ float d_T1[NXX * NXX];
__device__ float d_Ahat[NXX * NXX];
__device__ float d_Bhat[NXX * NWW];
__device__ float d_B2hat[NXX * NUU];
__device__ float d_fbhat[NXX];
__device__ float d_G1[BATCH * TSTEP * NWW];
__device__ float d_G2[BATCH * TSTEP * NXX];
__device__ float d_states[BATCH * TSTEP * NXX];
__device__ float d_Wb[BATCH * TSTEP * NWW];
__device__ float d_hbuf[NXX * BATCH];   // [x][b]
__device__ float d_wvec[NWW * BATCH];   // [j][b]
__device__ unsigned g_count;
__device__ unsigned g_release;

// ---------------- grid barrier helpers ----------------------------------------
__device__ __forceinline__ unsigned ld_acquire(unsigned* p) {
    unsigned v;
    asm volatile("ld.acquire.gpu.u32 %0, [%1];" : "=r"(v) : "l"(p) : "memory");
    return v;
}
__device__ __forceinline__ void st_release(unsigned* p, unsigned v) {
    asm volatile("st.release.gpu.u32 [%0], %1;" :: "l"(p), "r"(v) : "memory");
}
__device__ __forceinline__ void grid_barrier(unsigned gen) {
    __syncthreads();
    if (threadIdx.x == 0) {
        __threadfence();
        unsigned prev = atomicAdd(&g_count, 1u);
        if (prev + 1u == gen * (unsigned)gridDim.x) {
            st_release(&g_release, gen);
        } else {
            while (ld_acquire(&g_release) < gen) {}
        }
        __threadfence();
    }
    __syncthreads();
}

// ---------------- prep: Cv, Dv, X0 = 2I - E -----------------------------------
__global__ void prep_kernel(const float* __restrict__ C2, const float* __restrict__ mult,
                            const float* __restrict__ Dt, const float* __restrict__ E) {
    int i = blockIdx.x * blockDim.x + threadIdx.x;
    int stride = gridDim.x * blockDim.x;
    for (int idx = i; idx < NWW * NXX; idx += stride) {
        int r = idx / NXX;
        d_Cv[idx] = C2[idx] / mult[r];
    }
    for (int idx = i; idx < NWW * NUU; idx += stride) {
        int r = idx / NUU;
        d_Dv[idx] = Dt[idx] / mult[r];
    }
    for (int idx = i; idx < NXX * NXX; idx += stride) {
        int r = idx / NXX, c = idx % NXX;
        d_X[idx] = (r == c ? 2.0f : 0.0f) - E[idx];
    }
}

// M := 2I - M  (in place, 512x512)
__global__ void negI2_kernel(float* __restrict__ M) {
    int i = blockIdx.x * blockDim.x + threadIdx.x;
    int stride = gridDim.x * blockDim.x;
    for (int idx = i; idx < NXX * NXX; idx += stride) {
        int r = idx / NXX, c = idx % NXX;
        M[idx] = (r == c ? 2.0f : 0.0f) - M[idx];
    }
}

// ---------------- fp32 tiled GEMM: C(MxN) = A(MxK)@B(KxN), row-major ----------
__global__ void gemm_rrr(const float* __restrict__ A, const float* __restrict__ Bm,
                         float* __restrict__ C, int M, int N, int K) {
    __shared__ float As[16][64];
    __shared__ float Bs[16][64];
    int tid = threadIdx.x;
    int tx = tid & 15, ty = tid >> 4;
    int bx = blockIdx.x, by = blockIdx.y;
    float acc[4][4] = {};
    int ar = tid >> 2, ac = (tid & 3) << 2;
    int br = tid >> 4, bc = (tid & 15) << 2;
    for (int k0 = 0; k0 < K; k0 += 16) {
        float4 av = *(const float4*)&A[(size_t)(by * 64 + ar) * K + k0 + ac];
        As[ac + 0][ar] = av.x;
        As[ac + 1][ar] = av.y;
        As[ac + 2][ar] = av.z;
        As[ac + 3][ar] = av.w;
        *(float4*)&Bs[br][bc] = *(const float4*)&Bm[(size_t)(k0 + br) * N + bx * 64 + bc];
        __syncthreads();
#pragma unroll
        for (int k = 0; k < 16; k++) {
            float4 a = *(const float4*)&As[k][ty * 4];
            float4 b = *(const float4*)&Bs[k][tx * 4];
            acc[0][0] = fmaf(a.x, b.x, acc[0][0]); acc[0][1] = fmaf(a.x, b.y, acc[0][1]);
            acc[0][2] = fmaf(a.x, b.z, acc[0][2]); acc[0][3] = fmaf(a.x, b.w, acc[0][3]);
            acc[1][0] = fmaf(a.y, b.x, acc[1][0]); acc[1][1] = fmaf(a.y, b.y, acc[1][1]);
            acc[1][2] = fmaf(a.y, b.z, acc[1][2]); acc[1][3] = fmaf(a.y, b.w, acc[1][3]);
            acc[2][0] = fmaf(a.z, b.x, acc[2][0]); acc[2][1] = fmaf(a.z, b.y, acc[2][1]);
            acc[2][2] = fmaf(a.z, b.z, acc[2][2]); acc[2][3] = fmaf(a.z, b.w, acc[2][3]);
            acc[3][0] = fmaf(a.w, b.x, acc[3][0]); acc[3][1] = fmaf(a.w, b.y, acc[3][1]);
            acc[3][2] = fmaf(a.w, b.z, acc[3][2]); acc[3][3] = fmaf(a.w, b.w, acc[3][3]);
        }
        __syncthreads();
    }
#pragma unroll
    for (int i = 0; i < 4; i++) {
        float4 o = make_float4(acc[i][0], acc[i][1], acc[i][2], acc[i][3]);
        *(float4*)&C[(size_t)(by * 64 + ty * 4 + i) * N + bx * 64 + tx * 4] = o;
    }
}

// fbhat = Einv @ v
__global__ void matvec_kernel(const float* __restrict__ Einv, const float* __restrict__ v) {
    int r = blockIdx.x * blockDim.x + threadIdx.x;
    if (r < NXX) {
        float s = 0.f;
        for (int k = 0; k < NXX; k++) s = fmaf(Einv[(size_t)r * NXX + k], v[k], s);
        d_fbhat[r] = s;
    }
}

// ---------------- u projections: out[(b*T+t)*J + j] = bias[j] + sum_k u[b,k,t]*M[j,k]
__global__ void uproj_kernel(const float* __restrict__ u, const float* __restrict__ M,
                             const float* __restrict__ bias, float* __restrict__ out, int J) {
    __shared__ float U_s[NUU][65];  // [k][t]
    __shared__ float M_s[64][65];   // [j][k]
    int tid = threadIdx.x;
    int j0 = blockIdx.x * 64, t0 = blockIdx.y * 64, b = blockIdx.z;
    for (int i = tid; i < 64 * 64; i += 256) {
        int kk = i >> 6, tt = i & 63;
        U_s[kk][tt] = u[(size_t)b * NUU * TSTEP + (size_t)kk * TSTEP + t0 + tt];
    }
    for (int i = tid; i < 64 * 64; i += 256) {
        int j = i >> 6, k = i & 63;
        M_s[j][k] = M[(size_t)(j0 + j) * NUU + k];
    }
    __syncthreads();
    int lane = tid & 31, wg = tid >> 5;
    float acc0[8] = {}, acc1[8] = {};
    for (int k = 0; k < 64; k++) {
        float u0 = U_s[k][lane], u1 = U_s[k][lane + 32];
#pragma unroll
        for (int j = 0; j < 8; j++) {
            float m = M_s[wg * 8 + j][k];
            acc0[j] = fmaf(u0, m, acc0[j]);
            acc1[j] = fmaf(u1, m, acc1[j]);
        }
    }
    int jj0 = j0 + wg * 8;
    float bsv[8];
#pragma unroll
    for (int j = 0; j < 8; j++) bsv[j] = bias[jj0 + j];
    size_t r0 = ((size_t)b * TSTEP + t0 + lane) * J + jj0;
    size_t r1 = ((size_t)b * TSTEP + t0 + lane + 32) * J + jj0;
    *(float4*)&out[r0]     = make_float4(acc0[0] + bsv[0], acc0[1] + bsv[1], acc0[2] + bsv[2], acc0[3] + bsv[3]);
    *(float4*)&out[r0 + 4] = make_float4(acc0[4] + bsv[4], acc0[5] + bsv[5], acc0[6] + bsv[6], acc0[7] + bsv[7]);
    *(float4*)&out[r1]     = make_float4(acc1[0] + bsv[0], acc1[1] + bsv[1], acc1[2] + bsv[2], acc1[3] + bsv[3]);
    *(float4*)&out[r1 + 4] = make_float4(acc1[4] + bsv[4], acc1[5] + bsv[5], acc1[6] + bsv[6], acc1[7] + bsv[7]);
}

// ---------------- init: zero h0, states[:,0,:], reset barrier -----------------
__global__ void init_kernel() {
    int i = blockIdx.x * blockDim.x + threadIdx.x;
    int stride = gridDim.x * blockDim.x;
    if (i == 0) { g_count = 0u; g_release = 0u; }
    for (int idx = i; idx < NXX * BATCH; idx += stride) d_hbuf[idx] = 0.f;
    for (int idx = i; idx < BATCH * NXX; idx += stride) {
        int b = idx / NXX, x = idx % NXX;
        d_states[((size_t)b * TSTEP) * NXX + x] = 0.f;
    }
}

// ---------------- persistent sequential recurrence ----------------------------
// smem layout (floats): wAT[2048] | wBT[4096] | h_s[16384] | w_s[16384] | pbuf[1024]
__global__ void __launch_bounds__(RTHR, 1) recur_kernel() {
    extern __shared__ float smem[];
    float* wAT  = smem;                    // [k][c], k<512, c<4  (Cv rows of this CTA)
    float* wBT  = wAT + 4 * NXX;           // [k][c], k<1024     ([Ahat|Bhat] rows)
    float* h_s  = wBT + 4 * 1024;          // [k][b]  512 x 32
    float* w_s  = h_s + NXX * BATCH;       // [k][b]  512 x 32
    float* pbuf = w_s + NWW * BATCH;       // [warp][c][b] 8x4x32

    int tid = threadIdx.x;
    int cta = blockIdx.x;
    int warp = tid >> 5, lane = tid & 31;
    int j0 = cta * 4;

    // stage transposed weight slices (resident for whole kernel)
    for (int i = tid; i < 4 * NXX; i += RTHR) {
        int c = i >> 9, k = i & 511;
        wAT[k * 4 + c] = d_Cv[(size_t)(j0 + c) * NXX + k];
    }
    for (int i = tid; i < 4 * 1024; i += RTHR) {
        int c = i >> 10, k = i & 1023;
        wBT[k * 4 + c] = (k < NXX) ? d_Ahat[(size_t)(j0 + c) * NXX + k]
                                   : d_Bhat[(size_t)(j0 + c) * NWW + (k - NXX)];
    }
    __syncthreads();

    int cc = (tid < 128) ? (tid >> 5) : 0;
    int bb = tid & 31;
    unsigned gen = 0;

    for (int t = 0; t < TSTEP; t++) {
        // ======== phase A: w_t = relu(Cv @ h_t + G1[:,t]) ========
        float g1 = 0.f;
        if (tid < 128) g1 = d_G1[(bb * TSTEP + t) * NWW + j0 + cc];
        // each warp copies its own 64-k chunk of h
        {
            const float4* s4 = (const float4*)d_hbuf + warp * 512;
            float4* dd = (float4*)h_s + warp * 512;
#pragma unroll 8
            for (int i = lane; i < 512; i += 32) dd[i] = s4[i];
        }
        __syncwarp();
        {
            const float*  hs  = h_s + warp * 64 * BATCH;
            const float4* wv4 = (const float4*)(wAT + warp * 64 * 4);
            float a0 = 0.f, a1 = 0.f, a2 = 0.f, a3 = 0.f;
#pragma unroll 16
            for (int kk = 0; kk < 64; kk++) {
                float  hv = hs[kk * BATCH + lane];
                float4 wv = wv4[kk];
                a0 = fmaf(wv.x, hv, a0);
                a1 = fmaf(wv.y, hv, a1);
                a2 = fmaf(wv.z, hv, a2);
                a3 = fmaf(wv.w, hv, a3);
            }
            pbuf[warp * 128 + 0 * 32 + lane] = a0;
            pbuf[warp * 128 + 1 * 32 + lane] = a1;
            pbuf[warp * 128 + 2 * 32 + lane] = a2;
            pbuf[warp * 128 + 3 * 32 + lane] = a3;
        }
        __syncthreads();
        if (tid < 128) {
            float v = g1;
#pragma unroll
            for (int w = 0; w < 8; w++) v += pbuf[w * 128 + cc * 32 + bb];
            v = fmaxf(v, 0.f);
            d_wvec[(j0 + cc) * BATCH + bb] = v;
            d_Wb[(bb * TSTEP + t) * NWW + j0 + cc] = v;
        }
        if (t == TSTEP - 1) break;
        gen++; grid_barrier(gen);

        // ======== phase B: h_{t+1} = Ahat@h + Bhat@w + G2[:,t] ========
        float g2 = 0.f;
        if (tid < 128) g2 = d_G2[(bb * TSTEP + t) * NXX + j0 + cc];
        if (warp >= 4) {  // copy own 128-k chunk of w
            const float4* s4 = (const float4*)d_wvec + (warp - 4) * 1024;
            float4* dd = (float4*)w_s + (warp - 4) * 1024;
#pragma unroll 8
            for (int i = lane; i < 1024; i += 32) dd[i] = s4[i];
        }
        __syncwarp();
        {
            int kbase = (warp < 4) ? warp * 128 : NXX + (warp - 4) * 128;
            const float*  src = (warp < 4) ? (h_s + warp * 128 * BATCH)
                                           : (w_s + (warp - 4) * 128 * BATCH);
            const float4* wv4 = (const float4*)(wBT + kbase * 4);
            float a0 = 0.f, a1 = 0.f, a2 = 0.f, a3 = 0.f;
#pragma unroll 16
            for (int kk = 0; kk < 128; kk++) {
                float  hv = src[kk * BATCH + lane];
                float4 wv = wv4[kk];
                a0 = fmaf(wv.x, hv, a0);
                a1 = fmaf(wv.y, hv, a1);
                a2 = fmaf(wv.z, hv, a2);
                a3 = fmaf(wv.w, hv, a3);
            }
            pbuf[warp * 128 + 0 * 32 + lane] = a0;
            pbuf[warp * 128 + 1 * 32 + lane] = a1;
            pbuf[warp * 128 + 2 * 32 + lane] = a2;
            pbuf[warp * 128 + 3 * 32 + lane] = a3;
        }
        __syncthreads();
        if (tid < 128) {
            float v = g2;
#pragma unroll
            for (int w = 0; w < 8; w++) v += pbuf[w * 128 + cc * 32 + bb];
            d_hbuf[(j0 + cc) * BATCH + bb] = v;
            d_states[(bb * TSTEP + t + 1) * NXX + j0 + cc] = v;
        }
        gen++; grid_barrier(gen);
    }
}

// ---------------- epilogue: y = states@C1.T + W@D11.T + u@D12.T + by ----------
__global__ void yfinal_kernel(const float* __restrict__ u, const float* __restrict__ C1,
                              const float* __restrict__ D11, const float* __restrict__ D12,
                              const float* __restrict__ by, float* __restrict__ out) {
    __shared__ float As[64][65];  // [j][k]
    __shared__ float Bs[64][68];  // [k][t]  (68 keeps rows 16B aligned for float4)
    int tid = threadIdx.x;
    int tx = tid & 15, ty = tid >> 4;
    int t0 = blockIdx.x * 64, b = blockIdx.y;
    float acc[4][4] = {};
    for (int seg = 0; seg < 3; seg++) {
        int nchunk = (seg == 2) ? 1 : 8;
        const float* Am = (seg == 0) ? C1 : (seg == 1) ? D11 : D12;
        int Ksz = (seg == 2) ? 64 : 512;
        for (int ch = 0; ch < nchunk; ch++) {
            int x0 = ch * 64;
            for (int i = tid; i < 64 * 64; i += 256) {
                int j = i >> 6, k = i & 63;
                As[j][k] = Am[(size_t)j * Ksz + x0 + k];
            }
            if (seg == 2) {
                for (int i = tid; i < 64 * 64; i += 256) {
                    int k = i >> 6, tt = i & 63;
                    Bs[k][tt] = u[((size_t)b * NUU + k) * TSTEP + t0 + tt];
                }
            } else {
                const float* S = (seg == 0) ? d_states : d_Wb;
                for (int i = tid; i < 64 * 64; i += 256) {
                    int tt = i >> 6, xx = i & 63;
                    Bs[xx][tt] = S[((size_t)b * TSTEP + t0 + tt) * 512 + x0 + xx];
                }
            }
            __syncthreads();
#pragma unroll 8
            for (int k = 0; k < 64; k++) {
                float a0 = As[ty * 4 + 0][k];
                float a1 = As[ty * 4 + 1][k];
                float a2 = As[ty * 4 + 2][k];
                float a3 = As[ty * 4 + 3][k];
                float4 bv = *(const float4*)&Bs[k][tx * 4];
                acc[0][0] = fmaf(a0, bv.x, acc[0][0]); acc[0][1] = fmaf(a0, bv.y, acc[0][1]);
                acc[0][2] = fmaf(a0, bv.z, acc[0][2]); acc[0][3] = fmaf(a0, bv.w, acc[0][3]);
                acc[1][0] = fmaf(a1, bv.x, acc[1][0]); acc[1][1] = fmaf(a1, bv.y, acc[1][1]);
                acc[1][2] = fmaf(a1, bv.z, acc[1][2]); acc[1][3] = fmaf(a1, bv.w, acc[1][3]);
                acc[2][0] = fmaf(a2, bv.x, acc[2][0]); acc[2][1] = fmaf(a2, bv.y, acc[2][1]);
                acc[2][2] = fmaf(a2, bv.z, acc[2][2]); acc[2][3] = fmaf(a2, bv.w, acc[2][3]);
                acc[3][0] = fmaf(a3, bv.x, acc[3][0]); acc[3][1] = fmaf(a3, bv.y, acc[3][1]);
                acc[3][2] = fmaf(a3, bv.z, acc[3][2]); acc[3][3] = fmaf(a3, bv.w, acc[3][3]);
            }
            __syncthreads();
        }
    }
#pragma unroll
    for (int i = 0; i < 4; i++) {
        int j = ty * 4 + i;
        float bj = by[j];
        float4 o = make_float4(acc[i][0] + bj, acc[i][1] + bj, acc[i][2] + bj, acc[i][3] + bj);
        *(float4*)&out[((size_t)b * NYY + j) * TSTEP + t0 + tx * 4] = o;
    }
}

// ---------------- launch ------------------------------------------------------
extern "C" void kernel_launch(void* const* d_in, const int* in_sizes, int n_in,
                              void* d_out, int out_size) {
    const float* u      = (const float*)d_in[0];
    const float* E      = (const float*)d_in[1];
    const float* F_w    = (const float*)d_in[2];
    const float* F_b    = (const float*)d_in[3];
    const float* B1_w   = (const float*)d_in[4];
    const float* B2_w   = (const float*)d_in[5];
    const float* C2tild = (const float*)d_in[6];
    const float* bv     = (const float*)d_in[7];
    const float* Dtild  = (const float*)d_in[8];
    const float* C1_w   = (const float*)d_in[9];
    const float* D11_w  = (const float*)d_in[10];
    const float* D12_w  = (const float*)d_in[11];
    const float* by     = (const float*)d_in[12];
    const float* multis = (const float*)d_in[13];
    float* out = (float*)d_out;

    float *X, *X2, *T1, *Ahat, *Bhat, *B2hat, *Dv, *G1, *G2, *fbhat;
    cudaGetSymbolAddress((void**)&X,     d_X);
    cudaGetSymbolAddress((void**)&X2,    d_X2);
    cudaGetSymbolAddress((void**)&T1,    d_T1);
    cudaGetSymbolAddress((void**)&Ahat,  d_Ahat);
    cudaGetSymbolAddress((void**)&Bhat,  d_Bhat);
    cudaGetSymbolAddress((void**)&B2hat, d_B2hat);
    cudaGetSymbolAddress((void**)&Dv,    d_Dv);
    cudaGetSymbolAddress((void**)&G1,    d_G1);
    cudaGetSymbolAddress((void**)&G2,    d_G2);
    cudaGetSymbolAddress((void**)&fbhat, d_fbhat);

    const int SMEM_RECUR = (4 * NXX + 4 * 1024 + NXX * BATCH + NWW * BATCH + 1024) * 4;
    cudaFuncSetAttribute(recur_kernel, cudaFuncAttributeMaxDynamicSharedMemorySize, SMEM_RECUR);

    // 1) Cv, Dv, X0 = 2I - E
    prep_kernel<<<256, 256>>>(C2tild, multis, Dtild, E);

    // 2) Newton-Schulz: X <- X(2I - E X), 5 iterations
    dim3 g88(8, 8);
    for (int it = 0; it < 5; it++) {
        gemm_rrr<<<g88, 256>>>(E, X, T1, 512, 512, 512);
        negI2_kernel<<<256, 256>>>(T1);
        gemm_rrr<<<g88, 256>>>(X, T1, X2, 512, 512, 512);
        float* tmp = X; X = X2; X2 = tmp;
    }
    // X == Einv now

    // 3) folded weights
    gemm_rrr<<<g88, 256>>>(X, F_w, Ahat, 512, 512, 512);
    gemm_rrr<<<g88, 256>>>(X, B1_w, Bhat, 512, 512, 512);
    gemm_rrr<<<dim3(1, 8), 256>>>(X, B2_w, B2hat, 512, 64, 512);
    matvec_kernel<<<2, 256>>>(X, F_b);

    // 4) input-driven terms
    uproj_kernel<<<dim3(8, 16, 32), 256>>>(u, Dv, bv, G1, NWW);
    uproj_kernel<<<dim3(8, 16, 32), 256>>>(u, B2hat, fbhat, G2, NXX);

    // 5) init + sequential recurrence
    init_kernel<<<64, 256>>>();
    recur_kernel<<<RCTAS, RTHR, SMEM_RECUR>>>();

    // 6) epilogue
    yfinal_kernel<<<dim3(16, 32), 256>>>(u, C1_w, D11_w, D12_w, by, out);
}

// round 3
// speedup vs baseline: 1.8103x; 1.8103x over previous
#include <cuda_runtime.h>
#include <cstddef>

#define BATCH 32
#define NUU   64
#define NYY   64
#define NXX   512
#define NWW   512
#define TSTEP 1024
#define RCTAS 128
#define RTHR  256
#define GRPC  64     // CTAs per group
#define BG    16     // batches per group
#define PSTRIDE 144  // partial-buffer stride (bank-conflict-free padding)

// ---------------- device scratch (__device__ globals: allocation-free) --------
__device__ float d_Cv[NWW * NXX];
__device__ float d_Dv[NWW * NUU];
__device__ float d_X[NXX * NXX];
__device__ float d_X2[NXX * NXX];
__device__ float d_T1[NXX * NXX];
__device__ float d_Ahat[NXX * NXX];
__device__ float d_Bhat[NXX * NWW];
__device__ float d_B2hat[NXX * NUU];
__device__ float d_fbhat[NXX];
__device__ float d_G1[(size_t)TSTEP * BATCH * NWW];    // [t][b][j]
__device__ float d_G2[(size_t)TSTEP * BATCH * NXX];    // [t][b][x]
__device__ float d_states[(size_t)TSTEP * BATCH * NXX]; // [t][b][x]
__device__ float d_Wb[(size_t)TSTEP * BATCH * NWW];     // [t][b][j]
__device__ float d_hbuf[2 * NXX * BG];  // [g][x][b16]
__device__ float d_wvec[2 * NWW * BG];  // [g][j][b16]
__device__ unsigned g_cnt[2];

// ---------------- barrier primitives (fence-free release/acquire) -------------
__device__ __forceinline__ void bar_arrive(unsigned* cnt) {
    asm volatile("red.release.gpu.add.u32 [%0], 1;" :: "l"(cnt) : "memory");
}
__device__ __forceinline__ void bar_wait(unsigned* cnt, unsigned target) {
    if (threadIdx.x == 0) {
        unsigned v;
        do {
            asm volatile("ld.acquire.gpu.u32 %0, [%1];" : "=r"(v) : "l"(cnt) : "memory");
        } while (v < target);
    }
    __syncthreads();
}

// ---------------- prep: Cv, Dv, X0 = 2I - E -----------------------------------
__global__ void prep_kernel(const float* __restrict__ C2, const float* __restrict__ mult,
                            const float* __restrict__ Dt, const float* __restrict__ E) {
    int i = blockIdx.x * blockDim.x + threadIdx.x;
    int stride = gridDim.x * blockDim.x;
    for (int idx = i; idx < NWW * NXX; idx += stride) {
        int r = idx / NXX;
        d_Cv[idx] = C2[idx] / mult[r];
    }
    for (int idx = i; idx < NWW * NUU; idx += stride) {
        int r = idx / NUU;
        d_Dv[idx] = Dt[idx] / mult[r];
    }
    for (int idx = i; idx < NXX * NXX; idx += stride) {
        int r = idx / NXX, c = idx % NXX;
        d_X[idx] = (r == c ? 2.0f : 0.0f) - E[idx];
    }
}

// ---------------- fp32 tiled GEMM (ping-pong double buffered) -----------------
// mode 0: C = A@B      mode 1: C = 2I - A@B
__global__ void gemm_rrr(const float* __restrict__ A, const float* __restrict__ Bm,
                         float* __restrict__ C, int M, int N, int K, int mode) {
    __shared__ float As[2][16][64];
    __shared__ float Bs[2][16][64];
    int tid = threadIdx.x;
    int tx = tid & 15, ty = tid >> 4;
    int bx = blockIdx.x, by = blockIdx.y;
    int ar = tid >> 2, ac = (tid & 3) << 2;
    int br = tid >> 4, bc = (tid & 15) << 2;
    const float* Aptr = A + (size_t)(by * 64 + ar) * K + ac;
    const float* Bptr = Bm + (size_t)br * N + bx * 64 + bc;

    float4 av = *(const float4*)Aptr;
    float4 bv = *(const float4*)Bptr;
    As[0][ac + 0][ar] = av.x; As[0][ac + 1][ar] = av.y;
    As[0][ac + 2][ar] = av.z; As[0][ac + 3][ar] = av.w;
    *(float4*)&Bs[0][br][bc] = bv;
    __syncthreads();

    float acc[4][4] = {};
    int buf = 0;
    for (int k0 = 16; k0 <= K; k0 += 16) {
        if (k0 < K) {
            av = *(const float4*)(Aptr + k0);
            bv = *(const float4*)(Bptr + (size_t)k0 * N);
        }
#pragma unroll
        for (int k = 0; k < 16; k++) {
            float4 a = *(const float4*)&As[buf][k][ty * 4];
            float4 b = *(const float4*)&Bs[buf][k][tx * 4];
            acc[0][0] = fmaf(a.x, b.x, acc[0][0]); acc[0][1] = fmaf(a.x, b.y, acc[0][1]);
            acc[0][2] = fmaf(a.x, b.z, acc[0][2]); acc[0][3] = fmaf(a.x, b.w, acc[0][3]);
            acc[1][0] = fmaf(a.y, b.x, acc[1][0]); acc[1][1] = fmaf(a.y, b.y, acc[1][1]);
            acc[1][2] = fmaf(a.y, b.z, acc[1][2]); acc[1][3] = fmaf(a.y, b.w, acc[1][3]);
            acc[2][0] = fmaf(a.z, b.x, acc[2][0]); acc[2][1] = fmaf(a.z, b.y, acc[2][1]);
            acc[2][2] = fmaf(a.z, b.z, acc[2][2]); acc[2][3] = fmaf(a.z, b.w, acc[2][3]);
            acc[3][0] = fmaf(a.w, b.x, acc[3][0]); acc[3][1] = fmaf(a.w, b.y, acc[3][1]);
            acc[3][2] = fmaf(a.w, b.z, acc[3][2]); acc[3][3] = fmaf(a.w, b.w, acc[3][3]);
        }
        if (k0 < K) {
            int nb = buf ^ 1;
            As[nb][ac + 0][ar] = av.x; As[nb][ac + 1][ar] = av.y;
            As[nb][ac + 2][ar] = av.z; As[nb][ac + 3][ar] = av.w;
            *(float4*)&Bs[nb][br][bc] = bv;
        }
        __syncthreads();
        buf ^= 1;
    }
#pragma unroll
    for (int i = 0; i < 4; i++) {
        int r = by * 64 + ty * 4 + i;
        float o[4];
#pragma unroll
        for (int j = 0; j < 4; j++) {
            int cx = bx * 64 + tx * 4 + j;
            float v = acc[i][j];
            if (mode) v = (r == cx ? 2.0f : 0.0f) - v;
            o[j] = v;
        }
        *(float4*)&C[(size_t)r * N + bx * 64 + tx * 4] = make_float4(o[0], o[1], o[2], o[3]);
    }
}

// fbhat = Einv @ v
__global__ void matvec_kernel(const float* __restrict__ Einv, const float* __restrict__ v) {
    int r = blockIdx.x * blockDim.x + threadIdx.x;
    if (r < NXX) {
        float s = 0.f;
        for (int k = 0; k < NXX; k++) s = fmaf(Einv[(size_t)r * NXX + k], v[k], s);
        d_fbhat[r] = s;
    }
}

// ---------------- u projections: out[((t)*32 + b)*J + j] = bias[j] + sum_k u[b,k,t]*M[j,k]
__global__ void uproj_kernel(const float* __restrict__ u, const float* __restrict__ M,
                             const float* __restrict__ bias, float* __restrict__ out, int J) {
    __shared__ float U_s[NUU][65];  // [k][t]
    __shared__ float M_s[64][65];   // [j][k]
    int tid = threadIdx.x;
    int j0 = blockIdx.x * 64, t0 = blockIdx.y * 64, b = blockIdx.z;
    for (int i = tid; i < 64 * 64; i += 256) {
        int kk = i >> 6, tt = i & 63;
        U_s[kk][tt] = u[(size_t)b * NUU * TSTEP + (size_t)kk * TSTEP + t0 + tt];
    }
    for (int i = tid; i < 64 * 64; i += 256) {
        int j = i >> 6, k = i & 63;
        M_s[j][k] = M[(size_t)(j0 + j) * NUU + k];
    }
    __syncthreads();
    int lane = tid & 31, wg = tid >> 5;
    float acc0[8] = {}, acc1[8] = {};
    for (int k = 0; k < 64; k++) {
        float u0 = U_s[k][lane], u1 = U_s[k][lane + 32];
#pragma unroll
        for (int j = 0; j < 8; j++) {
            float m = M_s[wg * 8 + j][k];
            acc0[j] = fmaf(u0, m, acc0[j]);
            acc1[j] = fmaf(u1, m, acc1[j]);
        }
    }
    int jj0 = j0 + wg * 8;
    float bsv[8];
#pragma unroll
    for (int j = 0; j < 8; j++) bsv[j] = bias[jj0 + j];
    size_t r0 = ((size_t)(t0 + lane) * BATCH + b) * J + jj0;
    size_t r1 = ((size_t)(t0 + lane + 32) * BATCH + b) * J + jj0;
    *(float4*)&out[r0]     = make_float4(acc0[0] + bsv[0], acc0[1] + bsv[1], acc0[2] + bsv[2], acc0[3] + bsv[3]);
    *(float4*)&out[r0 + 4] = make_float4(acc0[4] + bsv[4], acc0[5] + bsv[5], acc0[6] + bsv[6], acc0[7] + bsv[7]);
    *(float4*)&out[r1]     = make_float4(acc1[0] + bsv[0], acc1[1] + bsv[1], acc1[2] + bsv[2], acc1[3] + bsv[3]);
    *(float4*)&out[r1 + 4] = make_float4(acc1[4] + bsv[4], acc1[5] + bsv[5], acc1[6] + bsv[6], acc1[7] + bsv[7]);
}

// ---------------- init: zero h0, states[t=0], reset barriers ------------------
__global__ void init_kernel() {
    int i = blockIdx.x * blockDim.x + threadIdx.x;
    int stride = gridDim.x * blockDim.x;
    if (i == 0) { g_cnt[0] = 0u; g_cnt[1] = 0u; }
    for (int idx = i; idx < 2 * NXX * BG; idx += stride) d_hbuf[idx] = 0.f;
    for (int idx = i; idx < BATCH * NXX; idx += stride) d_states[idx] = 0.f; // t=0 slab
}

// ---------------- recurrence inner dot: 8 rows x 32 k, one batch col ----------
__device__ __forceinline__ void dot_block(const float* __restrict__ hp,
                                          const float4* __restrict__ wq,
                                          float* __restrict__ pp) {
    float acc[8] = {};
#pragma unroll
    for (int kk = 0; kk < 32; kk++) {
        float hv = hp[kk * BG];
        float4 w0 = wq[2 * kk];
        float4 w1 = wq[2 * kk + 1];
        acc[0] = fmaf(w0.x, hv, acc[0]); acc[1] = fmaf(w0.y, hv, acc[1]);
        acc[2] = fmaf(w0.z, hv, acc[2]); acc[3] = fmaf(w0.w, hv, acc[3]);
        acc[4] = fmaf(w1.x, hv, acc[4]); acc[5] = fmaf(w1.y, hv, acc[5]);
        acc[6] = fmaf(w1.z, hv, acc[6]); acc[7] = fmaf(w1.w, hv, acc[7]);
    }
#pragma unroll
    for (int c = 0; c < 8; c++) pp[c * 16] = acc[c];
}

// ---------------- persistent sequential recurrence ----------------------------
// 2 groups x 64 CTAs; group g handles batches [16g,16g+16); CTA handles 8 rows.
__global__ void __launch_bounds__(RTHR, 1) recur_kernel() {
    extern __shared__ float smem[];
    float* wCv = smem;             // [512][8]  Cv^T slice
    float* wAh = wCv + 4096;       // [512][8]  Ahat^T
    float* wBh = wAh + 4096;       // [512][8]  Bhat^T
    float* h_s = wBh + 4096;       // [512][16]
    float* w_s = h_s + NXX * BG;   // [512][16]
    float* pW  = w_s + NWW * BG;   // [16][PSTRIDE]
    float* pA  = pW + 16 * PSTRIDE;
    float* pB  = pA + 16 * PSTRIDE;

    int tid = threadIdx.x;
    int cta = blockIdx.x;
    int g = cta >> 6;
    int j0 = (cta & 63) * 8;
    int warp = tid >> 5, lane = tid & 31;
    int b = lane & 15, kh = lane >> 4;
    int rrow = tid >> 4, rb = tid & 15;      // reduce mapping (tid<128)

    float* hg = d_hbuf + g * NXX * BG;
    float* wg = d_wvec + g * NWW * BG;
    unsigned* cnt = &g_cnt[g];

    // stage transposed weight slices (resident for whole kernel)
    for (int i = tid; i < 4096; i += RTHR) {
        int k = i >> 3, cc = i & 7;
        wCv[i] = d_Cv[(size_t)(j0 + cc) * NXX + k];
        wAh[i] = d_Ahat[(size_t)(j0 + cc) * NXX + k];
        wBh[i] = d_Bhat[(size_t)(j0 + cc) * NWW + k];
    }
    __syncthreads();

    int koff = (warp * 64 + kh * 32);

    for (int t = 0; t < TSTEP; t++) {
        // ---- wait for h(t) (skip t=0: init zeroed) ----
        if (t > 0) bar_wait(cnt, (unsigned)(2 * t) * GRPC);
        float g1 = 0.f;
        if (tid < 128) g1 = d_G1[((size_t)t * BATCH + g * BG + rb) * NWW + j0 + rrow];
        // copy own 64-k chunk of h (warp-local)
        {
            float4* dst = (float4*)(h_s + warp * 1024);
            const float4* src = (const float4*)(hg + warp * 1024);
#pragma unroll
            for (int i = 0; i < 8; i++) dst[lane + 32 * i] = src[lane + 32 * i];
        }
        __syncwarp();
        // ---- phase A: Cv @ h partials ----
        dot_block(h_s + koff * BG + b, (const float4*)(wCv + koff * 8),
                  pW + (warp * 2 + kh) * PSTRIDE + b);
        __syncthreads();
        if (tid < 128) {
            float v = g1;
#pragma unroll
            for (int p = 0; p < 16; p++) v += pW[p * PSTRIDE + rrow * 16 + rb];
            v = fmaxf(v, 0.f);
            wg[(j0 + rrow) * BG + rb] = v;
            d_Wb[((size_t)t * BATCH + g * BG + rb) * NWW + j0 + rrow] = v;
        }
        if (t == TSTEP - 1) break;
        __syncthreads();
        if (tid == 0) bar_arrive(cnt);               // w(t) ready: gen 2t+1
        float g2 = 0.f;
        if (tid < 128) g2 = d_G2[((size_t)t * BATCH + g * BG + rb) * NXX + j0 + rrow];
        // ---- Ahat @ h partials (hides the w barrier) ----
        dot_block(h_s + koff * BG + b, (const float4*)(wAh + koff * 8),
                  pA + (warp * 2 + kh) * PSTRIDE + b);
        // ---- wait for w(t) ----
        bar_wait(cnt, (unsigned)(2 * t + 1) * GRPC);
        // copy own 64-k chunk of w (warp-local)
        {
            float4* dst = (float4*)(w_s + warp * 1024);
            const float4* src = (const float4*)(wg + warp * 1024);
#pragma unroll
            for (int i = 0; i < 8; i++) dst[lane + 32 * i] = src[lane + 32 * i];
        }
        __syncwarp();
        // ---- Bhat @ w partials ----
        dot_block(w_s + koff * BG + b, (const float4*)(wBh + koff * 8),
                  pB + (warp * 2 + kh) * PSTRIDE + b);
        __syncthreads();
        // ---- reduce: h(t+1) ----
        if (tid < 128) {
            float v = g2;
#pragma unroll
            for (int p = 0; p < 16; p++)
                v += pA[p * PSTRIDE + rrow * 16 + rb] + pB[p * PSTRIDE + rrow * 16 + rb];
            hg[(j0 + rrow) * BG + rb] = v;
            d_states[((size_t)(t + 1) * BATCH + g * BG + rb) * NXX + j0 + rrow] = v;
        }
        __syncthreads();
        if (tid == 0) bar_arrive(cnt);               // h(t+1) ready: gen 2t+2
    }
}

// ---------------- epilogue: y = states@C1.T + W@D11.T + u@D12.T + by ----------
__global__ void yfinal_kernel(const float* __restrict__ u, const float* __restrict__ C1,
                              const float* __restrict__ D11, const float* __restrict__ D12,
                              const float* __restrict__ by, float* __restrict__ out) {
    __shared__ float As[64][65];  // [j][k]
    __shared__ float Bs[64][68];  // [k][t]
    int tid = threadIdx.x;
    int tx = tid & 15, ty = tid >> 4;
    int t0 = blockIdx.x * 64, b = blockIdx.y;
    float acc[4][4] = {};
    for (int seg = 0; seg < 3; seg++) {
        int nchunk = (seg == 2) ? 1 : 8;
        const float* Am = (seg == 0) ? C1 : (seg == 1) ? D11 : D12;
        int Ksz = (seg == 2) ? 64 : 512;
        for (int ch = 0; ch < nchunk; ch++) {
            int x0 = ch * 64;
            for (int i = tid; i < 64 * 64; i += 256) {
                int j = i >> 6, k = i & 63;
                As[j][k] = Am[(size_t)j * Ksz + x0 + k];
            }
            if (seg == 2) {
                for (int i = tid; i < 64 * 64; i += 256) {
                    int k = i >> 6, tt = i & 63;
                    Bs[k][tt] = u[((size_t)b * NUU + k) * TSTEP + t0 + tt];
                }
            } else {
                const float* S = (seg == 0) ? d_states : d_Wb;
                for (int i = tid; i < 64 * 64; i += 256) {
                    int tt = i >> 6, xx = i & 63;
                    Bs[xx][tt] = S[((size_t)(t0 + tt) * BATCH + b) * 512 + x0 + xx];
                }
            }
            __syncthreads();
#pragma unroll 8
            for (int k = 0; k < 64; k++) {
                float a0 = As[ty * 4 + 0][k];
                float a1 = As[ty * 4 + 1][k];
                float a2 = As[ty * 4 + 2][k];
                float a3 = As[ty * 4 + 3][k];
                float4 bv = *(const float4*)&Bs[k][tx * 4];
                acc[0][0] = fmaf(a0, bv.x, acc[0][0]); acc[0][1] = fmaf(a0, bv.y, acc[0][1]);
                acc[0][2] = fmaf(a0, bv.z, acc[0][2]); acc[0][3] = fmaf(a0, bv.w, acc[0][3]);
                acc[1][0] = fmaf(a1, bv.x, acc[1][0]); acc[1][1] = fmaf(a1, bv.y, acc[1][1]);
                acc[1][2] = fmaf(a1, bv.z, acc[1][2]); acc[1][3] = fmaf(a1, bv.w, acc[1][3]);
                acc[2][0] = fmaf(a2, bv.x, acc[2][0]); acc[2][1] = fmaf(a2, bv.y, acc[2][1]);
                acc[2][2] = fmaf(a2, bv.z, acc[2][2]); acc[2][3] = fmaf(a2, bv.w, acc[2][3]);
                acc[3][0] = fmaf(a3, bv.x, acc[3][0]); acc[3][1] = fmaf(a3, bv.y, acc[3][1]);
                acc[3][2] = fmaf(a3, bv.z, acc[3][2]); acc[3][3] = fmaf(a3, bv.w, acc[3][3]);
            }
            __syncthreads();
        }
    }
#pragma unroll
    for (int i = 0; i < 4; i++) {
        int j = ty * 4 + i;
        float bj = by[j];
        float4 o = make_float4(acc[i][0] + bj, acc[i][1] + bj, acc[i][2] + bj, acc[i][3] + bj);
        *(float4*)&out[((size_t)b * NYY + j) * TSTEP + t0 + tx * 4] = o;
    }
}

// ---------------- launch ------------------------------------------------------
extern "C" void kernel_launch(void* const* d_in, const int* in_sizes, int n_in,
                              void* d_out, int out_size) {
    const float* u      = (const float*)d_in[0];
    const float* E      = (const float*)d_in[1];
    const float* F_w    = (const float*)d_in[2];
    const float* F_b    = (const float*)d_in[3];
    const float* B1_w   = (const float*)d_in[4];
    const float* B2_w   = (const float*)d_in[5];
    const float* C2tild = (const float*)d_in[6];
    const float* bv     = (const float*)d_in[7];
    const float* Dtild  = (const float*)d_in[8];
    const float* C1_w   = (const float*)d_in[9];
    const float* D11_w  = (const float*)d_in[10];
    const float* D12_w  = (const float*)d_in[11];
    const float* by     = (const float*)d_in[12];
    const float* multis = (const float*)d_in[13];
    float* out = (float*)d_out;

    float *X, *X2, *T1, *Ahat, *Bhat, *B2hat, *Dv, *G1, *G2, *fbhat;
    cudaGetSymbolAddress((void**)&X,     d_X);
    cudaGetSymbolAddress((void**)&X2,    d_X2);
    cudaGetSymbolAddress((void**)&T1,    d_T1);
    cudaGetSymbolAddress((void**)&Ahat,  d_Ahat);
    cudaGetSymbolAddress((void**)&Bhat,  d_Bhat);
    cudaGetSymbolAddress((void**)&B2hat, d_B2hat);
    cudaGetSymbolAddress((void**)&Dv,    d_Dv);
    cudaGetSymbolAddress((void**)&G1,    d_G1);
    cudaGetSymbolAddress((void**)&G2,    d_G2);
    cudaGetSymbolAddress((void**)&fbhat, d_fbhat);

    const int SMEM_RECUR = (3 * 4096 + 2 * NXX * BG + 3 * 16 * PSTRIDE) * 4;
    cudaFuncSetAttribute(recur_kernel, cudaFuncAttributeMaxDynamicSharedMemorySize, SMEM_RECUR);

    // 1) Cv, Dv, X0 = 2I - E
    prep_kernel<<<256, 256>>>(C2tild, multis, Dtild, E);

    // 2) Newton-Schulz: X <- X(2I - E X), 4 iterations
    dim3 g88(8, 8);
    for (int it = 0; it < 4; it++) {
        gemm_rrr<<<g88, 256>>>(E, X, T1, 512, 512, 512, 1);   // T1 = 2I - E@X
        gemm_rrr<<<g88, 256>>>(X, T1, X2, 512, 512, 512, 0);
        float* tmp = X; X = X2; X2 = tmp;
    }
    // X == Einv

    // 3) folded weights
    gemm_rrr<<<g88, 256>>>(X, F_w, Ahat, 512, 512, 512, 0);
    gemm_rrr<<<g88, 256>>>(X, B1_w, Bhat, 512, 512, 512, 0);
    gemm_rrr<<<dim3(1, 8), 256>>>(X, B2_w, B2hat, 512, 64, 512, 0);
    matvec_kernel<<<2, 256>>>(X, F_b);

    // 4) input-driven terms: G1[t][b][j], G2[t][b][x]
    uproj_kernel<<<dim3(8, 16, 32), 256>>>(u, Dv, bv, G1, NWW);
    uproj_kernel<<<dim3(8, 16, 32), 256>>>(u, B2hat, fbhat, G2, NXX);

    // 5) init + sequential recurrence
    init_kernel<<<64, 256>>>();
    recur_kernel<<<RCTAS, RTHR, SMEM_RECUR>>>();

    // 6) epilogue
    yfinal_kernel<<<dim3(16, 32), 256>>>(u, C1_w, D11_w, D12_w, by, out);
}